// round 14
// baseline (speedup 1.0000x reference)
#include <cuda_runtime.h>
#include <cuda_fp16.h>

// actor_53781580480512 R14: R13 with the sigmoid-argument bug fixed.
//  - w3h = g2*W3 (1x: 2x rsqrt-fold x 0.5 arg-halving), bb3h = 0.5*b3f
//    so pre = 0.5*o_full; sigmoid = pre*Q(pre^2) + 0.5 with Q = P/2.
//  - LN mean-subtract as fma(sum,-0.25,h); balanced var trees, eps in leaf
//  - L1/L2 tanh on MUFU; #pragma unroll 2; __launch_bounds__(256,3)
//   B=4096, Z=64, P=4096, H=4, BTILE=64, grid 64x64.

#define ZDIM 64
#define PDIM 4096
#define BTILE 64

__device__ __forceinline__ __half2 tanh2(__half2 v) {
    unsigned vi = *reinterpret_cast<unsigned*>(&v), ri;
    asm("tanh.approx.f16x2 %0, %1;" : "=r"(ri) : "r"(vi));
    return *reinterpret_cast<__half2*>(&ri);
}

__global__ __launch_bounds__(256, 3)
void actor_mlp_kernel(
    const float* __restrict__ x,
    const float* __restrict__ W1, const float* __restrict__ b1,
    const float* __restrict__ g1, const float* __restrict__ be1,
    const float* __restrict__ W2, const float* __restrict__ b2,
    const float* __restrict__ g2, const float* __restrict__ be2,
    const float* __restrict__ W3, const float* __restrict__ b3,
    float* __restrict__ out, int B)
{
    const int zp = threadIdx.x & 63;        // 0..63
    const int bl = threadIdx.x >> 6;        // 0..3
    const int z  = blockIdx.x;              // 0..63
    const int b0 = blockIdx.y * BTILE;
    const int p  = z * ZDIM + zp;

    // ================= prologue: load + fold (once per 16 b) ================
    __half2 w1h[8], bb1h[4];
    {
        float4 a = __ldg((const float4*)&W1[p * 8]);
        float4 c = __ldg((const float4*)&W1[p * 8 + 4]);
        w1h[0]=__float2half2_rn(a.x); w1h[1]=__float2half2_rn(a.y);
        w1h[2]=__float2half2_rn(a.z); w1h[3]=__float2half2_rn(a.w);
        w1h[4]=__float2half2_rn(c.x); w1h[5]=__float2half2_rn(c.y);
        w1h[6]=__float2half2_rn(c.z); w1h[7]=__float2half2_rn(c.w);
        float4 bv = __ldg((const float4*)&b1[p * 4]);
        bb1h[0]=__float2half2_rn(bv.x); bb1h[1]=__float2half2_rn(bv.y);
        bb1h[2]=__float2half2_rn(bv.z); bb1h[3]=__float2half2_rn(bv.w);
    }

    __half2 w2h[16], bb2h[4], w3h[4], bb3h;
    {
        float4 g1v  = __ldg((const float4*)&g1 [p * 4]);
        float4 be1v = __ldg((const float4*)&be1[p * 4]);
        float gg1[4]  = {2.0f*g1v.x, 2.0f*g1v.y, 2.0f*g1v.z, 2.0f*g1v.w};
        float bbe1[4] = {be1v.x, be1v.y, be1v.z, be1v.w};
        float4 b2v = __ldg((const float4*)&b2[p * 4]);
        float b2f[4] = {b2v.x, b2v.y, b2v.z, b2v.w};
#pragma unroll
        for (int i = 0; i < 4; i++) {
            float4 wr = __ldg((const float4*)&W2[p * 16 + i * 4]);
            float wrow[4] = {wr.x, wr.y, wr.z, wr.w};
#pragma unroll
            for (int j = 0; j < 4; j++) {
                w2h[i * 4 + j] = __float2half2_rn(gg1[i] * wrow[j]);
                b2f[j] = fmaf(bbe1[i], wrow[j], b2f[j]);
            }
        }
#pragma unroll
        for (int j = 0; j < 4; j++) bb2h[j] = __float2half2_rn(b2f[j]);

        float4 g2v  = __ldg((const float4*)&g2 [p * 4]);
        float4 be2v = __ldg((const float4*)&be2[p * 4]);
        float4 w3v  = __ldg((const float4*)&W3 [p * 4]);
        // 2x (rsqrt fold) * 0.5 (sigmoid arg-halving) = 1x
        w3h[0] = __float2half2_rn(g2v.x * w3v.x);
        w3h[1] = __float2half2_rn(g2v.y * w3v.y);
        w3h[2] = __float2half2_rn(g2v.z * w3v.z);
        w3h[3] = __float2half2_rn(g2v.w * w3v.w);
        float b3f = __ldg(&b3[p]);
        b3f = fmaf(be2v.x, w3v.x, b3f);
        b3f = fmaf(be2v.y, w3v.y, b3f);
        b3f = fmaf(be2v.z, w3v.z, b3f);
        b3f = fmaf(be2v.w, w3v.w, b3f);
        bb3h = __float2half2_rn(0.5f * b3f);   // pre = 0.5 * o_full
    }

    const __half2 cNQ   = __float2half2_rn(-0.25f);
    const __half2 cEps4 = __float2half2_rn(4e-5f);
    const __half2 cH    = __float2half2_rn(0.5f);

    // 0.5*tanh(x) ~= x * Q(x^2) on [-2,2], Q = P/2 (deg-9 odd Chebyshev base)
    const __half2 cLo = __float2half2_rn(-2.0f);
    const __half2 cHi = __float2half2_rn( 2.0f);
    const __half2 B0  = __float2half2_rn( 0.499470f);
    const __half2 B1  = __float2half2_rn(-0.1590620f);
    const __half2 B2  = __float2half2_rn( 0.0486650f);
    const __half2 B3  = __float2half2_rn(-0.00921675f);
    const __half2 B4  = __float2half2_rn( 0.00073920f);

    const float* xpa = x + (b0 + 4 * bl) * ZDIM + z;
    const float* xpc = x + (b0 + 4 * bl) * ZDIM + zp;
    float*       opt = out + (b0 + 4 * bl) * PDIM + p;

    // ============ main loop: 4 b-elements / thread / iteration ==============
#pragma unroll 2
    for (int it = 0; it < BTILE / 16; it++) {        // 4 iterations
        float xa[4], xc[4];
#pragma unroll
        for (int u = 0; u < 4; u++) {
            xa[u] = __ldg(xpa + u * ZDIM);           // warp-uniform, L1-hot
            xc[u] = __ldg(xpc + u * ZDIM);           // coalesced
        }
        xpa += 16 * ZDIM; xpc += 16 * ZDIM;

        float o[4];
#pragma unroll
        for (int u = 0; u < 2; u++) {                // 2 independent chains
            __half2 xa2 = __floats2half2_rn(xa[2*u], xa[2*u+1]);
            __half2 xc2 = __floats2half2_rn(xc[2*u], xc[2*u+1]);

            // layer 1 + tanh (MUFU)
            __half2 h[4];
#pragma unroll
            for (int j = 0; j < 4; j++)
                h[j] = tanh2(__hfma2(xa2, w1h[j],
                             __hfma2(xc2, w1h[4 + j], bb1h[j])));

            // LN1: d_i = fma(sum, -0.25, h_i); balanced var tree, eps in leaf
            __half2 sum = __hadd2(__hadd2(h[0], h[1]), __hadd2(h[2], h[3]));
            __half2 d0 = __hfma2(sum, cNQ, h[0]);
            __half2 d1 = __hfma2(sum, cNQ, h[1]);
            __half2 d2 = __hfma2(sum, cNQ, h[2]);
            __half2 d3 = __hfma2(sum, cNQ, h[3]);
            __half2 va = __hfma2(d0, d0, __hmul2(d1, d1));
            __half2 vb = __hfma2(d2, d2, __hfma2(d3, d3, cEps4));
            __half2 r  = h2rsqrt(__hadd2(va, vb));

            // layer 2 + tanh (MUFU)
            __half2 k[4];
#pragma unroll
            for (int j = 0; j < 4; j++) {
                __half2 dot = __hmul2(d0, w2h[j]);
                dot = __hfma2(d1, w2h[4 + j], dot);
                dot = __hfma2(d2, w2h[8 + j], dot);
                dot = __hfma2(d3, w2h[12 + j], dot);
                k[j] = tanh2(__hfma2(r, dot, bb2h[j]));
            }

            // LN2
            __half2 sum2 = __hadd2(__hadd2(k[0], k[1]), __hadd2(k[2], k[3]));
            __half2 e0 = __hfma2(sum2, cNQ, k[0]);
            __half2 e1 = __hfma2(sum2, cNQ, k[1]);
            __half2 e2 = __hfma2(sum2, cNQ, k[2]);
            __half2 e3 = __hfma2(sum2, cNQ, k[3]);
            __half2 wa = __hfma2(e0, e0, __hmul2(e1, e1));
            __half2 wb = __hfma2(e2, e2, __hfma2(e3, e3, cEps4));
            __half2 r2 = h2rsqrt(__hadd2(wa, wb));

            // layer 3 + sigmoid: pre = 0.5*o; og = clamp(pre)*Q(.) + 0.5
            __half2 dot3 = __hmul2(e0, w3h[0]);
            dot3 = __hfma2(e1, w3h[1], dot3);
            dot3 = __hfma2(e2, w3h[2], dot3);
            dot3 = __hfma2(e3, w3h[3], dot3);
            __half2 pre = __hfma2(r2, dot3, bb3h);
            __half2 xx  = __hmin2(__hmax2(pre, cLo), cHi);
            __half2 t   = __hmul2(xx, xx);
            __half2 q   = __hfma2(t, B4, B3);
            q = __hfma2(t, q, B2);
            q = __hfma2(t, q, B1);
            q = __hfma2(t, q, B0);
            __half2 og  = __hfma2(xx, q, cH);

            float2 of = __half22float2(og);
            o[2*u] = of.x; o[2*u+1] = of.y;
        }

#pragma unroll
        for (int u = 0; u < 4; u++)
            opt[u * PDIM] = o[u];
        opt += 16 * PDIM;
    }
}

extern "C" void kernel_launch(void* const* d_in, const int* in_sizes, int n_in,
                              void* d_out, int out_size)
{
    const float* x   = (const float*)d_in[0];
    const float* W1  = (const float*)d_in[1];
    const float* b1  = (const float*)d_in[2];
    const float* g1  = (const float*)d_in[3];
    const float* be1 = (const float*)d_in[4];
    const float* W2  = (const float*)d_in[5];
    const float* b2  = (const float*)d_in[6];
    const float* g2  = (const float*)d_in[7];
    const float* be2 = (const float*)d_in[8];
    const float* W3  = (const float*)d_in[9];
    const float* b3  = (const float*)d_in[10];
    float* out = (float*)d_out;

    int B = in_sizes[0] / ZDIM;
    dim3 grid(ZDIM, (B + BTILE - 1) / BTILE);   // 64 x 64 = 4096 CTAs
    actor_mlp_kernel<<<grid, 256>>>(x, W1, b1, g1, be1, W2, b2, g2, be2,
                                    W3, b3, out, B);
}

// round 15
// speedup vs baseline: 1.0498x; 1.0498x over previous
#include <cuda_runtime.h>
#include <cuda_fp16.h>

// actor_53781580480512 R15: explicit 4-chain ILP (8 b-elems/thread/iter, 2 iters)
// + zero-sum LN fold (sum(d)=0 => fold w2/w3 row differences, drop d3/e3 terms).
//   B=4096, Z=64, P=4096, H=4, BTILE=64, grid 64x64, 3 CTAs/SM.

#define ZDIM 64
#define PDIM 4096
#define BTILE 64

__device__ __forceinline__ __half2 tanh2(__half2 v) {
    unsigned vi = *reinterpret_cast<unsigned*>(&v), ri;
    asm("tanh.approx.f16x2 %0, %1;" : "=r"(ri) : "r"(vi));
    return *reinterpret_cast<__half2*>(&ri);
}

__global__ __launch_bounds__(256, 3)
void actor_mlp_kernel(
    const float* __restrict__ x,
    const float* __restrict__ W1, const float* __restrict__ b1,
    const float* __restrict__ g1, const float* __restrict__ be1,
    const float* __restrict__ W2, const float* __restrict__ b2,
    const float* __restrict__ g2, const float* __restrict__ be2,
    const float* __restrict__ W3, const float* __restrict__ b3,
    float* __restrict__ out, int B)
{
    const int zp = threadIdx.x & 63;        // 0..63
    const int bl = threadIdx.x >> 6;        // 0..3
    const int z  = blockIdx.x;              // 0..63
    const int b0 = blockIdx.y * BTILE;
    const int p  = z * ZDIM + zp;

    // ================= prologue: load + fold (once per 16 b) ================
    __half2 w1h[8], bb1h[4];
    {
        float4 a = __ldg((const float4*)&W1[p * 8]);
        float4 c = __ldg((const float4*)&W1[p * 8 + 4]);
        w1h[0]=__float2half2_rn(a.x); w1h[1]=__float2half2_rn(a.y);
        w1h[2]=__float2half2_rn(a.z); w1h[3]=__float2half2_rn(a.w);
        w1h[4]=__float2half2_rn(c.x); w1h[5]=__float2half2_rn(c.y);
        w1h[6]=__float2half2_rn(c.z); w1h[7]=__float2half2_rn(c.w);
        float4 bv = __ldg((const float4*)&b1[p * 4]);
        bb1h[0]=__float2half2_rn(bv.x); bb1h[1]=__float2half2_rn(bv.y);
        bb1h[2]=__float2half2_rn(bv.z); bb1h[3]=__float2half2_rn(bv.w);
    }

    // w2d[i][j] = (2*g1[i]*W2[i][j]) - (2*g1[3]*W2[3][j])  (i=0..2)
    __half2 w2d[12], bb2h[4], w3d[3], bb3h;
    {
        float4 g1v  = __ldg((const float4*)&g1 [p * 4]);
        float4 be1v = __ldg((const float4*)&be1[p * 4]);
        float gg1[4]  = {2.0f*g1v.x, 2.0f*g1v.y, 2.0f*g1v.z, 2.0f*g1v.w};
        float bbe1[4] = {be1v.x, be1v.y, be1v.z, be1v.w};
        float4 b2v = __ldg((const float4*)&b2[p * 4]);
        float b2f[4] = {b2v.x, b2v.y, b2v.z, b2v.w};
        float w2f[4][4];
#pragma unroll
        for (int i = 0; i < 4; i++) {
            float4 wr = __ldg((const float4*)&W2[p * 16 + i * 4]);
            float wrow[4] = {wr.x, wr.y, wr.z, wr.w};
#pragma unroll
            for (int j = 0; j < 4; j++) {
                w2f[i][j] = gg1[i] * wrow[j];
                b2f[j] = fmaf(bbe1[i], wrow[j], b2f[j]);
            }
        }
#pragma unroll
        for (int i = 0; i < 3; i++)
#pragma unroll
            for (int j = 0; j < 4; j++)
                w2d[i * 4 + j] = __float2half2_rn(w2f[i][j] - w2f[3][j]);
#pragma unroll
        for (int j = 0; j < 4; j++) bb2h[j] = __float2half2_rn(b2f[j]);

        float4 g2v  = __ldg((const float4*)&g2 [p * 4]);
        float4 be2v = __ldg((const float4*)&be2[p * 4]);
        float4 w3v  = __ldg((const float4*)&W3 [p * 4]);
        // 2x (rsqrt fold) * 0.5 (sigmoid arg-halving) = 1x
        float w3f[4] = {g2v.x * w3v.x, g2v.y * w3v.y,
                        g2v.z * w3v.z, g2v.w * w3v.w};
        w3d[0] = __float2half2_rn(w3f[0] - w3f[3]);
        w3d[1] = __float2half2_rn(w3f[1] - w3f[3]);
        w3d[2] = __float2half2_rn(w3f[2] - w3f[3]);
        float b3f = __ldg(&b3[p]);
        b3f = fmaf(be2v.x, w3v.x, b3f);
        b3f = fmaf(be2v.y, w3v.y, b3f);
        b3f = fmaf(be2v.z, w3v.z, b3f);
        b3f = fmaf(be2v.w, w3v.w, b3f);
        bb3h = __float2half2_rn(0.5f * b3f);   // pre = 0.5 * o_full
    }

    const __half2 cNQ   = __float2half2_rn(-0.25f);
    const __half2 cEps4 = __float2half2_rn(4e-5f);
    const __half2 cH    = __float2half2_rn(0.5f);

    // 0.5*tanh(x) ~= x * Q(x^2) on [-2,2]
    const __half2 cLo = __float2half2_rn(-2.0f);
    const __half2 cHi = __float2half2_rn( 2.0f);
    const __half2 B0  = __float2half2_rn( 0.499470f);
    const __half2 B1  = __float2half2_rn(-0.1590620f);
    const __half2 B2  = __float2half2_rn( 0.0486650f);
    const __half2 B3  = __float2half2_rn(-0.00921675f);
    const __half2 B4  = __float2half2_rn( 0.00073920f);

    const float* xpa = x + (b0 + 8 * bl) * ZDIM + z;
    const float* xpc = x + (b0 + 8 * bl) * ZDIM + zp;
    float*       opt = out + (b0 + 8 * bl) * PDIM + p;

    // ====== main loop: 8 b-elements (4 explicit chains) / thread / iter =====
#pragma unroll 1
    for (int it = 0; it < 2; it++) {
        // pack inputs for 4 chains
        __half2 XA[4], XC[4];
#pragma unroll
        for (int u = 0; u < 4; u++) {
            float a0 = __ldg(xpa + (2*u    ) * ZDIM);
            float a1 = __ldg(xpa + (2*u + 1) * ZDIM);
            float c0 = __ldg(xpc + (2*u    ) * ZDIM);
            float c1 = __ldg(xpc + (2*u + 1) * ZDIM);
            XA[u] = __floats2half2_rn(a0, a1);
            XC[u] = __floats2half2_rn(c0, c1);
        }
        xpa += 32 * ZDIM; xpc += 32 * ZDIM;

        __half2 OG[4];
#pragma unroll
        for (int u = 0; u < 4; u++) {                // 4 independent chains
            // layer 1 + tanh (MUFU)
            __half2 h0 = tanh2(__hfma2(XA[u], w1h[0], __hfma2(XC[u], w1h[4], bb1h[0])));
            __half2 h1 = tanh2(__hfma2(XA[u], w1h[1], __hfma2(XC[u], w1h[5], bb1h[1])));
            __half2 h2 = tanh2(__hfma2(XA[u], w1h[2], __hfma2(XC[u], w1h[6], bb1h[2])));
            __half2 h3 = tanh2(__hfma2(XA[u], w1h[3], __hfma2(XC[u], w1h[7], bb1h[3])));

            // LN1: d_i = fma(sum,-0.25,h_i); var balanced tree, eps in leaf
            __half2 sum = __hadd2(__hadd2(h0, h1), __hadd2(h2, h3));
            __half2 d0 = __hfma2(sum, cNQ, h0);
            __half2 d1 = __hfma2(sum, cNQ, h1);
            __half2 d2 = __hfma2(sum, cNQ, h2);
            __half2 d3 = __hfma2(sum, cNQ, h3);
            __half2 va = __hfma2(d0, d0, __hmul2(d1, d1));
            __half2 vb = __hfma2(d2, d2, __hfma2(d3, d3, cEps4));
            __half2 r  = h2rsqrt(__hadd2(va, vb));

            // layer 2 (zero-sum fold: only d0..d2 against difference weights)
            __half2 k0, k1, k2, k3;
            {
                __half2 t0 = __hmul2(d0, w2d[0]);
                t0 = __hfma2(d1, w2d[4], t0);
                t0 = __hfma2(d2, w2d[8], t0);
                k0 = tanh2(__hfma2(r, t0, bb2h[0]));
                __half2 t1 = __hmul2(d0, w2d[1]);
                t1 = __hfma2(d1, w2d[5], t1);
                t1 = __hfma2(d2, w2d[9], t1);
                k1 = tanh2(__hfma2(r, t1, bb2h[1]));
                __half2 t2 = __hmul2(d0, w2d[2]);
                t2 = __hfma2(d1, w2d[6], t2);
                t2 = __hfma2(d2, w2d[10], t2);
                k2 = tanh2(__hfma2(r, t2, bb2h[2]));
                __half2 t3 = __hmul2(d0, w2d[3]);
                t3 = __hfma2(d1, w2d[7], t3);
                t3 = __hfma2(d2, w2d[11], t3);
                k3 = tanh2(__hfma2(r, t3, bb2h[3]));
            }

            // LN2
            __half2 sum2 = __hadd2(__hadd2(k0, k1), __hadd2(k2, k3));
            __half2 e0 = __hfma2(sum2, cNQ, k0);
            __half2 e1 = __hfma2(sum2, cNQ, k1);
            __half2 e2 = __hfma2(sum2, cNQ, k2);
            __half2 e3 = __hfma2(sum2, cNQ, k3);
            __half2 wa = __hfma2(e0, e0, __hmul2(e1, e1));
            __half2 wb = __hfma2(e2, e2, __hfma2(e3, e3, cEps4));
            __half2 r2 = h2rsqrt(__hadd2(wa, wb));

            // layer 3 (zero-sum fold) + sigmoid poly (pre = 0.5*o_full)
            __half2 dot3 = __hmul2(e0, w3d[0]);
            dot3 = __hfma2(e1, w3d[1], dot3);
            dot3 = __hfma2(e2, w3d[2], dot3);
            __half2 pre = __hfma2(r2, dot3, bb3h);
            __half2 xx  = __hmin2(__hmax2(pre, cLo), cHi);
            __half2 t   = __hmul2(xx, xx);
            __half2 q   = __hfma2(t, B4, B3);
            q = __hfma2(t, q, B2);
            q = __hfma2(t, q, B1);
            q = __hfma2(t, q, B0);
            OG[u] = __hfma2(xx, q, cH);
        }

#pragma unroll
        for (int u = 0; u < 4; u++) {
            float2 of = __half22float2(OG[u]);
            opt[(2*u    ) * PDIM] = of.x;
            opt[(2*u + 1) * PDIM] = of.y;
        }
        opt += 32 * PDIM;
    }
}

extern "C" void kernel_launch(void* const* d_in, const int* in_sizes, int n_in,
                              void* d_out, int out_size)
{
    const float* x   = (const float*)d_in[0];
    const float* W1  = (const float*)d_in[1];
    const float* b1  = (const float*)d_in[2];
    const float* g1  = (const float*)d_in[3];
    const float* be1 = (const float*)d_in[4];
    const float* W2  = (const float*)d_in[5];
    const float* b2  = (const float*)d_in[6];
    const float* g2  = (const float*)d_in[7];
    const float* be2 = (const float*)d_in[8];
    const float* W3  = (const float*)d_in[9];
    const float* b3  = (const float*)d_in[10];
    float* out = (float*)d_out;

    int B = in_sizes[0] / ZDIM;
    dim3 grid(ZDIM, (B + BTILE - 1) / BTILE);   // 64 x 64 = 4096 CTAs
    actor_mlp_kernel<<<grid, 256>>>(x, W1, b1, g1, be1, W2, b2, g2, be2,
                                    W3, b3, out, B);
}